// round 10
// baseline (speedup 1.0000x reference)
#include <cuda_runtime.h>
#include <cstdint>

// ============================================================================
// SpectralNetLoss:
//   2n·loss = Σ_ij W_ij(sq_i + sq_j) − 2 Σ_ij W_ij (y_i·y_j)
// One tf32 mma.sync GEMM U = W × B̃,  B̃ = [Y | sq | 1 | 0…] (72 cols).
// R10: no in-loop CVT (raw-bit A truncation, B rna-packed); k-slot remap
//      (2q,2q+1) -> A via conflict-free LDS.64 (RS=40); B fragment-pairs via
//      LDG.128; single barrier/chunk; 4-stage depth-3 cp.async pipeline.
// ============================================================================

#define N_DIM     8192
#define KF        64
#define M_TILE    128
#define KCHUNK    32
#define KSPLIT    9
#define RS        40                        // row stride: 8 mod 32 words -> CF
#define NFRAG     9

#define A_FLOATS  (M_TILE * RS)             // 5120
#define STAGE_BYTES  (A_FLOATS * 4)         // 20480
#define N_STAGES  4
#define SMEM_BYTES   (N_STAGES * STAGE_BYTES)  // 81920

#define NCK       (N_DIM / 8)               // 1024 k-octets
#define CK_BYTES  2304                      // 4 pair-blocks(512B) + single(256B)

// B̃ packed per k-octet ck (k slots 2q,2q+1):
//  pair p (frags 2p,2p+1): float4[lane] = (f2p.k0, f2p.k1, f2p+1.k0, f2p+1.k1)
//  single (frag 8, cols 64..71): float2[lane]
__device__ float g_Bp[(size_t)NCK * (CK_BYTES / 4)];
__device__ float g_sq[N_DIM];

// ---------------------------------------------------------------- helpers
__device__ __forceinline__ uint32_t smem_u32(const void* p) {
    uint32_t a;
    asm("{ .reg .u64 t; cvta.to.shared.u64 t, %1; cvt.u32.u64 %0, t; }"
        : "=r"(a) : "l"(p));
    return a;
}
__device__ __forceinline__ void cp_async16(uint32_t dst, const void* src) {
    asm volatile("cp.async.cg.shared.global [%0], [%1], 16;"
                 :: "r"(dst), "l"(src));
}
__device__ __forceinline__ void cp_commit() {
    asm volatile("cp.async.commit_group;" ::: "memory");
}
__device__ __forceinline__ void cp_wait2() {
    asm volatile("cp.async.wait_group 2;" ::: "memory");
}
__device__ __forceinline__ uint32_t tf32r(float f) {
    uint32_t r;
    asm("cvt.rna.tf32.f32 %0, %1;" : "=r"(r) : "f"(f));
    return r;
}
__device__ __forceinline__ void mma_tf32(float* c, const uint32_t* a,
                                         uint32_t b0, uint32_t b1) {
    asm volatile(
        "mma.sync.aligned.m16n8k8.row.col.f32.tf32.tf32.f32 "
        "{%0,%1,%2,%3}, {%4,%5,%6,%7}, {%8,%9}, {%0,%1,%2,%3};"
        : "+f"(c[0]), "+f"(c[1]), "+f"(c[2]), "+f"(c[3])
        : "r"(a[0]), "r"(a[1]), "r"(a[2]), "r"(a[3]), "r"(b0), "r"(b1));
}

// ---------------------------------------------------------------- fused prep
// Block b: k-rows [b*32, b*32+32) -> sq + packed B̃ (4 k-octets).
__global__ void spec_prep(const float* __restrict__ Y, float* __restrict__ out) {
    __shared__ float sY[32 * 72];
    __shared__ float ssq[32];
    const int tid = threadIdx.x;
    const int b = blockIdx.x;
    const int k0 = b * 32;

    if (b == 0 && tid == 0) out[0] = 0.0f;

#pragma unroll
    for (int i = 0; i < 8; i++) {
        int idx = tid + i * 256;
        sY[(idx >> 6) * 72 + (idx & 63)] = Y[(size_t)k0 * KF + idx];
    }
    __syncthreads();

    {   // sq: 8 threads per row
        int r = tid >> 3, p = tid & 7;
        const float* row = sY + r * 72 + p * 8;
        float s = 0.0f;
#pragma unroll
        for (int c = 0; c < 8; c++) s += row[c] * row[c];
#pragma unroll
        for (int o = 4; o; o >>= 1) s += __shfl_xor_sync(0xffffffffu, s, o);
        if (p == 0) { ssq[r] = s; g_sq[k0 + r] = s; }
    }
    __syncthreads();

    // pair blocks: 4 ck × 4 pairs × 32 lanes = 512 float4 writes
#pragma unroll
    for (int i = 0; i < 2; i++) {
        int pw = tid + i * 256;
        int lane = pw & 31;
        int p = (pw >> 5) & 3;
        int ckl = pw >> 7;
        int q = lane & 3, g = lane >> 2;
        int ka = ckl * 8 + 2 * q, kb = ka + 1;
        int n0 = 16 * p + g, n1 = n0 + 8;
        float4 v;
        v.x = __uint_as_float(tf32r(sY[ka * 72 + n0]));
        v.y = __uint_as_float(tf32r(sY[kb * 72 + n0]));
        v.z = __uint_as_float(tf32r(sY[ka * 72 + n1]));
        v.w = __uint_as_float(tf32r(sY[kb * 72 + n1]));
        *(float4*)((char*)g_Bp + (size_t)(b * 4 + ckl) * CK_BYTES + p * 512 +
                   lane * 16) = v;
    }
    // single block: 4 ck × 32 lanes float2
    if (tid < 128) {
        int lane = tid & 31;
        int ckl = tid >> 5;
        int q = lane & 3, g = lane >> 2;
        int ka = ckl * 8 + 2 * q, kb = ka + 1;
        float2 v;
        v.x = (g == 0) ? __uint_as_float(tf32r(ssq[ka])) : (g == 1 ? 1.0f : 0.0f);
        v.y = (g == 0) ? __uint_as_float(tf32r(ssq[kb])) : (g == 1 ? 1.0f : 0.0f);
        *(float2*)((char*)g_Bp + (size_t)(b * 4 + ckl) * CK_BYTES + 2048 +
                   lane * 8) = v;
    }
}

// ---------------------------------------------------------------- A loader
__device__ __forceinline__ void load_chunk(uint32_t sdst, const float* wp,
                                           int tid) {
#pragma unroll
    for (int u = 0; u < 4; u++) {
        int idx = tid + u * 256;                      // 128 rows x 8 float4
        int r = idx >> 3, sg = idx & 7;
        cp_async16(sdst + (uint32_t)(r * RS + sg * 4) * 4,
                   wp + (size_t)r * N_DIM + sg * 4);
    }
}

// ---------------------------------------------------------------- main
__global__ void __launch_bounds__(256, 2)
spec_main(const float* __restrict__ W, const float* __restrict__ Y,
          float* __restrict__ out) {
    extern __shared__ float smem[];
    const uint32_t sb = smem_u32(smem);

    const int tid = threadIdx.x;
    const int w   = tid >> 5;
    const int lid = tid & 31;
    const int q   = lid & 3;
    const int g   = lid >> 2;
    const int mg  = w & 3;             // 32-row group (one per SMSP)
    const int ng  = w >> 2;            // 0: frags 0..3 | 1: frags 4..8

    const int bx    = blockIdx.x;
    const int mtile = bx & 63;
    const int ks    = bx >> 6;
    const int m0    = mtile * M_TILE;
    const int c0    = (ks < 4) ? ks * 29 : 116 + (ks - 4) * 28;
    const int nch   = (ks < 4) ? 29 : 28;

    const float* wbase = W + (size_t)m0 * N_DIM + (size_t)c0 * KCHUNK;
    const char*  bpb   = (const char*)g_Bp + (ng ? 1024 : 0) + lid * 16;
    const char*  bpe   = (const char*)g_Bp + 2048 + lid * 8;

    float acc[2][4][4];
    float acc_e[2][4];
#pragma unroll
    for (int mt = 0; mt < 2; mt++) {
#pragma unroll
        for (int nt = 0; nt < 4; nt++)
#pragma unroll
            for (int v = 0; v < 4; v++) acc[mt][nt][v] = 0.0f;
#pragma unroll
        for (int v = 0; v < 4; v++) acc_e[mt][v] = 0.0f;
    }

    // prologue: 3 chunks in flight
#pragma unroll
    for (int p = 0; p < 3; p++) {
        load_chunk(sb + p * STAGE_BYTES, wbase + (size_t)p * KCHUNK, tid);
        cp_commit();
    }

    for (int j = 0; j < nch; j++) {
        cp_wait2();                        // chunk j resident
        __syncthreads();                   // also guards stage reuse (j-1 read)
        if (j + 3 < nch)
            load_chunk(sb + ((j + 3) & 3) * STAGE_BYTES,
                       wbase + (size_t)(j + 3) * KCHUNK, tid);
        cp_commit();                       // empty group keeps count aligned

        const float* As = smem + (j & 3) * A_FLOATS;
        const int cb = (c0 + j) * 4;

#pragma unroll
        for (int kst = 0; kst < 4; kst++) {
            const size_t ckoff = (size_t)(cb + kst) * CK_BYTES;
            // B fragments: 2x LDG.128 (+LDG.64 for ng1), L1/L2-hot
            float4 P0 = *(const float4*)(bpb + ckoff);
            float4 P1 = *(const float4*)(bpb + ckoff + 512);
            float2 E;
            if (ng) E = *(const float2*)(bpe + ckoff);

            // A fragments: 4x conflict-free LDS.64, raw f32 bits (HW tf32)
            const int k0 = kst * 8 + 2 * q;
            uint32_t a[2][4];
#pragma unroll
            for (int mt = 0; mt < 2; mt++) {
                const float* ap = As + (mg * 32 + mt * 16 + g) * RS + k0;
                float2 lo = *(const float2*)ap;
                float2 hi = *(const float2*)(ap + 8 * RS);
                a[mt][0] = __float_as_uint(lo.x);
                a[mt][1] = __float_as_uint(hi.x);
                a[mt][2] = __float_as_uint(lo.y);
                a[mt][3] = __float_as_uint(hi.y);
            }
#pragma unroll
            for (int mt = 0; mt < 2; mt++) {
                mma_tf32(acc[mt][0], a[mt], __float_as_uint(P0.x),
                                            __float_as_uint(P0.y));
                mma_tf32(acc[mt][1], a[mt], __float_as_uint(P0.z),
                                            __float_as_uint(P0.w));
                mma_tf32(acc[mt][2], a[mt], __float_as_uint(P1.x),
                                            __float_as_uint(P1.y));
                mma_tf32(acc[mt][3], a[mt], __float_as_uint(P1.z),
                                            __float_as_uint(P1.w));
            }
            if (ng) {
#pragma unroll
                for (int mt = 0; mt < 2; mt++)
                    mma_tf32(acc_e[mt], a[mt], __float_as_uint(E.x),
                                               __float_as_uint(E.y));
            }
        }
    }

    // ------------- epilogue: fold U with Y + extra cols, reduce -------------
    const int rbase = m0 + mg * 32 + g;
    float sqi[2][2];
    sqi[0][0] = g_sq[rbase];      sqi[0][1] = g_sq[rbase + 8];
    sqi[1][0] = g_sq[rbase + 16]; sqi[1][1] = g_sq[rbase + 24];

    float dot = 0.0f, extra = 0.0f;
#pragma unroll
    for (int mt = 0; mt < 2; mt++) {
        const int r0 = m0 + mg * 32 + mt * 16 + g;
#pragma unroll
        for (int nt = 0; nt < 4; nt++) {
            const int cc = ng * 32 + nt * 8 + 2 * q;
            float2 y0 = *(const float2*)(Y + (size_t)r0 * KF + cc);
            float2 y1 = *(const float2*)(Y + (size_t)(r0 + 8) * KF + cc);
            dot += acc[mt][nt][0] * y0.x + acc[mt][nt][1] * y0.y +
                   acc[mt][nt][2] * y1.x + acc[mt][nt][3] * y1.y;
        }
        if (ng) {
            // q==0 lanes: col64=(W·sq)_i (v0/v2), col65=rowsum r_i (v1/v3);
            // q>=1 lanes hold zero columns -> exact 0.
            extra += acc_e[mt][0] + sqi[mt][0] * acc_e[mt][1] +
                     acc_e[mt][2] + sqi[mt][1] * acc_e[mt][3];
        }
    }
    float total = extra - 2.0f * dot;
#pragma unroll
    for (int o = 16; o; o >>= 1)
        total += __shfl_xor_sync(0xffffffffu, total, o);

    __syncthreads();                   // stages dead; reuse smem for reduction
    if (lid == 0) smem[w] = total;
    __syncthreads();
    if (tid == 0) {
        float s = 0.0f;
#pragma unroll
        for (int i = 0; i < 8; i++) s += smem[i];
        atomicAdd(out, s * (1.0f / (2.0f * (float)N_DIM)));
    }
}

// ---------------------------------------------------------------- launch
extern "C" void kernel_launch(void* const* d_in, const int* in_sizes, int n_in,
                              void* d_out, int out_size) {
    const float* W = (const float*)d_in[0];
    const float* Y = (const float*)d_in[1];
    float* out = (float*)d_out;

    cudaFuncSetAttribute(spec_main, cudaFuncAttributeMaxDynamicSharedMemorySize,
                         SMEM_BYTES);

    spec_prep<<<N_DIM / 32, 256>>>(Y, out);
    spec_main<<<64 * KSPLIT, 256, SMEM_BYTES>>>(W, Y, out);
}

// round 11
// speedup vs baseline: 1.4724x; 1.4724x over previous
#include <cuda_runtime.h>
#include <cstdint>

// ============================================================================
// SpectralNetLoss:
//   2n·loss = Σ_ij W_ij(sq_i + sq_j) − 2 Σ_ij W_ij (y_i·y_j)
// Term 1: in-loop fp32 FFMA on W fragments (R4-proven, keeps rel_err ~1e-7).
// Term 2: tf32 mma.sync GEMM U = W × Yt folded with Y.
// R11 = R4 base (128 thr, 4 warps, 2Mx8N tile, q/q+4 slots, 2-barrier chunk)
//   + packed-global B pair-blocks (4x LDG.128/kst, L1-hot, CK=2048)
//   + A-only 3-stage cp.async pipeline + KSPLIT=9 + fused fast prep.
// ============================================================================

#define N_DIM     8192
#define KF        64
#define M_TILE    128
#define KCHUNK    32
#define KSPLIT    9
#define RS        36                        // R4-proven padded A row stride

#define A_FLOATS  (M_TILE * RS)             // 4608
#define SQ_OFF    A_FLOATS
#define STAGE_FLOATS (A_FLOATS + 32)        // 4640
#define STAGE_BYTES  (STAGE_FLOATS * 4)     // 18560
#define N_STAGES  3
#define SMEM_BYTES   (N_STAGES * STAGE_BYTES)  // 55680 (x4 CTA = 222.7KB)

#define NCK       (N_DIM / 8)               // 1024 k-octets
#define CK_BYTES  2048                      // 4 pair-blocks x 512B

// B packed per k-octet ck, R4 slot convention (q, q+4):
//  pair p (frags 2p,2p+1): float4[lane g*4+q] =
//    ( Y[k+q][16p+g], Y[k+q+4][16p+g], Y[k+q][16p+8+g], Y[k+q+4][16p+8+g] )
//  with k = ck*8.  Values rna-rounded to tf32.
__device__ float g_Bp[(size_t)NCK * (CK_BYTES / 4)];
__device__ float g_sq[N_DIM];

// ---------------------------------------------------------------- helpers
__device__ __forceinline__ uint32_t smem_u32(const void* p) {
    uint32_t a;
    asm("{ .reg .u64 t; cvta.to.shared.u64 t, %1; cvt.u32.u64 %0, t; }"
        : "=r"(a) : "l"(p));
    return a;
}
__device__ __forceinline__ void cp_async16(uint32_t dst, const void* src) {
    asm volatile("cp.async.cg.shared.global [%0], [%1], 16;"
                 :: "r"(dst), "l"(src));
}
__device__ __forceinline__ void cp_commit() {
    asm volatile("cp.async.commit_group;" ::: "memory");
}
__device__ __forceinline__ void cp_wait2() {
    asm volatile("cp.async.wait_group 2;" ::: "memory");
}
__device__ __forceinline__ uint32_t tf32r(float f) {
    uint32_t r;
    asm("cvt.rna.tf32.f32 %0, %1;" : "=r"(r) : "f"(f));
    return r;
}
__device__ __forceinline__ void mma_tf32(float* c, const uint32_t* a,
                                         uint32_t b0, uint32_t b1) {
    asm volatile(
        "mma.sync.aligned.m16n8k8.row.col.f32.tf32.tf32.f32 "
        "{%0,%1,%2,%3}, {%4,%5,%6,%7}, {%8,%9}, {%0,%1,%2,%3};"
        : "+f"(c[0]), "+f"(c[1]), "+f"(c[2]), "+f"(c[3])
        : "r"(a[0]), "r"(a[1]), "r"(a[2]), "r"(a[3]), "r"(b0), "r"(b1));
}

// ---------------------------------------------------------------- fused prep
// Block b: k-rows [b*32, b*32+32) -> sq + packed B (4 k-octets).
__global__ void spec_prep(const float* __restrict__ Y, float* __restrict__ out) {
    __shared__ float sY[32 * 72];           // stride 72: conflict-free reads
    __shared__ float ssq[32];
    const int tid = threadIdx.x;
    const int b = blockIdx.x;
    const int k0 = b * 32;

    if (b == 0 && tid == 0) out[0] = 0.0f;

#pragma unroll
    for (int i = 0; i < 8; i++) {
        int idx = tid + i * 256;            // coalesced 32x64 load
        sY[(idx >> 6) * 72 + (idx & 63)] = Y[(size_t)k0 * KF + idx];
    }
    __syncthreads();

    {   // sq: 8 threads per row
        int r = tid >> 3, p = tid & 7;
        const float* row = sY + r * 72 + p * 8;
        float s = 0.0f;
#pragma unroll
        for (int c = 0; c < 8; c++) s += row[c] * row[c];
#pragma unroll
        for (int o = 4; o; o >>= 1) s += __shfl_xor_sync(0xffffffffu, s, o);
        if (p == 0) { ssq[r] = s; g_sq[k0 + r] = s; }
    }
    __syncthreads();

    // pair blocks: 4 ck x 4 pairs x 32 lanes = 512 float4 writes (coalesced)
#pragma unroll
    for (int i = 0; i < 2; i++) {
        int u = tid + i * 256;
        int lane = u & 31;
        int p = (u >> 5) & 3;
        int ckl = u >> 7;                   // 0..3
        int q = lane & 3, g = lane >> 2;
        int ka = ckl * 8 + q, kb = ka + 4;  // R4 slot convention
        int n0 = 16 * p + g, n1 = n0 + 8;
        float4 v;
        v.x = __uint_as_float(tf32r(sY[ka * 72 + n0]));
        v.y = __uint_as_float(tf32r(sY[kb * 72 + n0]));
        v.z = __uint_as_float(tf32r(sY[ka * 72 + n1]));
        v.w = __uint_as_float(tf32r(sY[kb * 72 + n1]));
        *(float4*)((char*)g_Bp + (size_t)(b * 4 + ckl) * CK_BYTES + p * 512 +
                   lane * 16) = v;
    }
}

// ---------------------------------------------------------------- A loader
__device__ __forceinline__ void load_chunk(uint32_t sdst, const float* wp,
                                           const float* sp, int tid) {
#pragma unroll
    for (int u = 0; u < 8; u++) {
        int idx = tid + u * 128;                      // 128 rows x 8 float4
        int r = idx >> 3, sg = idx & 7;
        cp_async16(sdst + (uint32_t)(r * RS + sg * 4) * 4,
                   wp + (size_t)r * N_DIM + sg * 4);
    }
    if (tid < 8)
        cp_async16(sdst + SQ_OFF * 4 + tid * 16, sp + tid * 4);
}

// ---------------------------------------------------------------- main
__global__ void __launch_bounds__(128, 4)
spec_main(const float* __restrict__ W, const float* __restrict__ Y,
          float* __restrict__ out) {
    extern __shared__ float smem[];
    const uint32_t sb = smem_u32(smem);

    const int tid = threadIdx.x;
    const int w   = tid >> 5;          // warp 0..3: rows [w*32, w*32+32)
    const int lid = tid & 31;
    const int q   = lid & 3;
    const int g   = lid >> 2;
    const int w32 = w * 32;

    const int bx    = blockIdx.x;
    const int mtile = bx & 63;
    const int ks    = bx >> 6;                              // 0..8
    const int m0    = mtile * M_TILE;
    const int c0    = (ks < 4) ? ks * 29 : 116 + (ks - 4) * 28;
    const int nch   = (ks < 4) ? 29 : 28;

    const float* wbase = W + (size_t)m0 * N_DIM + (size_t)c0 * KCHUNK;
    const char*  bpb   = (const char*)g_Bp + lid * 16;

    // row squared-norms for this thread's 4 fragment rows
    const int rbase = m0 + w32 + g;
    float sqi[2][2];
    sqi[0][0] = g_sq[rbase];      sqi[0][1] = g_sq[rbase + 8];
    sqi[1][0] = g_sq[rbase + 16]; sqi[1][1] = g_sq[rbase + 24];

    float acc[2][8][4];
#pragma unroll
    for (int mt = 0; mt < 2; mt++)
#pragma unroll
        for (int nt = 0; nt < 8; nt++)
#pragma unroll
            for (int v = 0; v < 4; v++) acc[mt][nt][v] = 0.0f;
    float scal = 0.0f;

    // prologue: chunks 0,1 in flight
    load_chunk(sb, wbase, g_sq + (size_t)c0 * KCHUNK, tid);
    cp_commit();
    load_chunk(sb + STAGE_BYTES, wbase + KCHUNK,
               g_sq + (size_t)(c0 + 1) * KCHUNK, tid);
    cp_commit();

    for (int j = 0; j < nch; j++) {
        if (j + 2 < nch)
            load_chunk(sb + ((j + 2) % 3) * STAGE_BYTES,
                       wbase + (size_t)(j + 2) * KCHUNK,
                       g_sq + (size_t)(c0 + j + 2) * KCHUNK, tid);
        cp_commit();                      // empty groups keep count aligned
        cp_wait2();                       // chunk j resident
        __syncthreads();

        const float* As = smem + (j % 3) * STAGE_FLOATS;
        const float* Ss = As + SQ_OFF;
        const int cb = (c0 + j) * 4;

#pragma unroll
        for (int kst = 0; kst < 4; kst++) {
            const int k0 = kst * 8;
            const size_t ckoff = (size_t)(cb + kst) * CK_BYTES;
            // B: 4x coalesced LDG.128 pair-blocks (L1-hot, shared by all warps)
            float4 P0 = *(const float4*)(bpb + ckoff);
            float4 P1 = *(const float4*)(bpb + ckoff + 512);
            float4 P2 = *(const float4*)(bpb + ckoff + 1024);
            float4 P3 = *(const float4*)(bpb + ckoff + 1536);

            const float sq0 = Ss[k0 + q];
            const float sq1 = Ss[k0 + q + 4];
            uint32_t a[2][4];
#pragma unroll
            for (int mt = 0; mt < 2; mt++) {
                const float* ap = As + (w32 + mt * 16 + g) * RS + k0 + q;
                float a0 = ap[0];
                float a1 = ap[8 * RS];
                float a2 = ap[4];
                float a3 = ap[8 * RS + 4];
                scal += a0 * (sqi[mt][0] + sq0) + a2 * (sqi[mt][0] + sq1) +
                        a1 * (sqi[mt][1] + sq0) + a3 * (sqi[mt][1] + sq1);
                a[mt][0] = __float_as_uint(a0);
                a[mt][1] = __float_as_uint(a1);
                a[mt][2] = __float_as_uint(a2);
                a[mt][3] = __float_as_uint(a3);
            }
#pragma unroll
            for (int mt = 0; mt < 2; mt++) {
                mma_tf32(acc[mt][0], a[mt], __float_as_uint(P0.x),
                                            __float_as_uint(P0.y));
                mma_tf32(acc[mt][1], a[mt], __float_as_uint(P0.z),
                                            __float_as_uint(P0.w));
                mma_tf32(acc[mt][2], a[mt], __float_as_uint(P1.x),
                                            __float_as_uint(P1.y));
                mma_tf32(acc[mt][3], a[mt], __float_as_uint(P1.z),
                                            __float_as_uint(P1.w));
                mma_tf32(acc[mt][4], a[mt], __float_as_uint(P2.x),
                                            __float_as_uint(P2.y));
                mma_tf32(acc[mt][5], a[mt], __float_as_uint(P2.z),
                                            __float_as_uint(P2.w));
                mma_tf32(acc[mt][6], a[mt], __float_as_uint(P3.x),
                                            __float_as_uint(P3.y));
                mma_tf32(acc[mt][7], a[mt], __float_as_uint(P3.z),
                                            __float_as_uint(P3.w));
            }
        }
        __syncthreads();
    }

    // ------------- epilogue: fold U with Y, reduce to scalar ---------------
    float dot = 0.0f;
#pragma unroll
    for (int mt = 0; mt < 2; mt++) {
        const int r0 = m0 + w32 + mt * 16 + g;
#pragma unroll
        for (int nt = 0; nt < 8; nt++) {
            const int cc = nt * 8 + 2 * q;
            float2 y0 = *(const float2*)(Y + (size_t)r0 * KF + cc);
            float2 y1 = *(const float2*)(Y + (size_t)(r0 + 8) * KF + cc);
            dot += acc[mt][nt][0] * y0.x + acc[mt][nt][1] * y0.y +
                   acc[mt][nt][2] * y1.x + acc[mt][nt][3] * y1.y;
        }
    }
    float total = scal - 2.0f * dot;
#pragma unroll
    for (int o = 16; o; o >>= 1)
        total += __shfl_xor_sync(0xffffffffu, total, o);

    if (lid == 0) smem[w] = total;     // stages dead after final chunk barrier
    __syncthreads();
    if (tid == 0) {
        atomicAdd(out, (smem[0] + smem[1] + smem[2] + smem[3]) *
                           (1.0f / (2.0f * (float)N_DIM)));
    }
}

// ---------------------------------------------------------------- launch
extern "C" void kernel_launch(void* const* d_in, const int* in_sizes, int n_in,
                              void* d_out, int out_size) {
    const float* W = (const float*)d_in[0];
    const float* Y = (const float*)d_in[1];
    float* out = (float*)d_out;

    cudaFuncSetAttribute(spec_main, cudaFuncAttributeMaxDynamicSharedMemorySize,
                         SMEM_BYTES);

    spec_prep<<<N_DIM / 32, 256>>>(Y, out);
    spec_main<<<64 * KSPLIT, 128, SMEM_BYTES>>>(W, Y, out);
}

// round 12
// speedup vs baseline: 2.6147x; 1.7758x over previous
#include <cuda_runtime.h>
#include <cstdint>

// ============================================================================
// SpectralNetLoss:
//   2n·loss = Σ_ij W_ij(sq_i + sq_j) − 2 Σ_ij W_ij (y_i·y_j)
// Term 1: in-loop fp32 FFMA on W fragments (exact; dominates the loss).
// Term 2: bf16 mma.sync m16n8k16 GEMM U = W × Y folded with Y (dot term is
//         ~1e-4 of the loss; bf16 noise on it is ~1e-8 relative on the loss).
// R12 = R4 structure (128 thr, 4 warps, 2Mx8N tile, 2-stage cp.async, two
//   barriers/chunk) + bf16 MMA (half the HMMAs) + B pre-packed as bf16
//   fragments in GMEM, staged via cp.async, read by ONE conflict-free LDS.64
//   + RS=40 (conflict-free paired-k A LDS.64) + KSPLIT=9 + fused prep.
// ============================================================================

#define N_DIM     8192
#define KF        64
#define M_TILE    128
#define KCHUNK    32
#define KSPLIT    9
#define RS        40                        // (4g+q) mod 16 distinct -> CF LDS.64

#define A_FLOATS  (M_TILE * RS)             // 5120
#define SQ_OFF    A_FLOATS                  // 32 floats of sq_k
#define B_OFF     ((A_FLOATS + 32) * 4)     // byte offset of B pack: 20608
#define B_BYTES   4096                      // 2 kst16 x 8 nt x 32 lanes x 8B
#define STAGE_BYTES  (B_OFF + B_BYTES)      // 24704
#define STAGE_FLOATS (STAGE_BYTES / 4)      // 6176
#define SMEM_BYTES   (2 * STAGE_BYTES)      // 49408 (x4 CTA = 197.6KB)

// B packed per chunk c: [kst16][nt][lane] -> uint2{ b0 = bf16x2(k=2q,2q+1),
//   b1 = bf16x2(k=2q+8,2q+9) } at col n = nt*8+g, k rel = kst*16 + ...
__device__ float g_Bp[(size_t)N_DIM * KF / 2];     // 1MB bf16
__device__ float g_sq[N_DIM];

// ---------------------------------------------------------------- helpers
__device__ __forceinline__ uint32_t smem_u32(const void* p) {
    uint32_t a;
    asm("{ .reg .u64 t; cvta.to.shared.u64 t, %1; cvt.u32.u64 %0, t; }"
        : "=r"(a) : "l"(p));
    return a;
}
__device__ __forceinline__ void cp_async16(uint32_t dst, const void* src) {
    asm volatile("cp.async.cg.shared.global [%0], [%1], 16;"
                 :: "r"(dst), "l"(src));
}
__device__ __forceinline__ void cp_commit() {
    asm volatile("cp.async.commit_group;" ::: "memory");
}
__device__ __forceinline__ void cp_wait1() {
    asm volatile("cp.async.wait_group 1;" ::: "memory");
}
__device__ __forceinline__ void cp_wait0() {
    asm volatile("cp.async.wait_group 0;" ::: "memory");
}
__device__ __forceinline__ uint32_t bf16pair(float lo, float hi) {
    uint32_t r;   // hi -> upper 16, lo -> lower 16
    asm("cvt.rn.bf16x2.f32 %0, %1, %2;" : "=r"(r) : "f"(hi), "f"(lo));
    return r;
}
__device__ __forceinline__ void mma_bf16(float* c, const uint32_t* a,
                                         uint32_t b0, uint32_t b1) {
    asm volatile(
        "mma.sync.aligned.m16n8k16.row.col.f32.bf16.bf16.f32 "
        "{%0,%1,%2,%3}, {%4,%5,%6,%7}, {%8,%9}, {%0,%1,%2,%3};"
        : "+f"(c[0]), "+f"(c[1]), "+f"(c[2]), "+f"(c[3])
        : "r"(a[0]), "r"(a[1]), "r"(a[2]), "r"(a[3]), "r"(b0), "r"(b1));
}

// ---------------------------------------------------------------- fused prep
// Block b handles k-rows [b*32, b*32+32): sq + bf16 fragment pack of B chunk b.
__global__ void spec_prep(const float* __restrict__ Y, float* __restrict__ out) {
    __shared__ float sY[32 * 72];           // [k][n], stride 72
    const int tid = threadIdx.x;
    const int b = blockIdx.x;
    const int k0g = b * 32;

    if (b == 0 && tid == 0) out[0] = 0.0f;

#pragma unroll
    for (int i = 0; i < 8; i++) {
        int idx = tid + i * 256;            // coalesced 32x64 load
        sY[(idx >> 6) * 72 + (idx & 63)] = Y[(size_t)k0g * KF + idx];
    }
    __syncthreads();

    {   // sq: 8 threads per row
        int r = tid >> 3, p = tid & 7;
        const float* row = sY + r * 72 + p * 8;
        float s = 0.0f;
#pragma unroll
        for (int c = 0; c < 8; c++) s += row[c] * row[c];
#pragma unroll
        for (int o = 4; o; o >>= 1) s += __shfl_xor_sync(0xffffffffu, s, o);
        if (p == 0) g_sq[k0g + r] = s;
    }

    // fragment pack: 512 uint2 per chunk, 2 per thread (coalesced 8B writes)
#pragma unroll
    for (int i = 0; i < 2; i++) {
        int u = tid + i * 256;              // [kst][nt][lane]
        int lane = u & 31;
        int nt   = (u >> 5) & 7;
        int kst  = u >> 8;
        int q = lane & 3, g = lane >> 2;
        int n  = nt * 8 + g;
        int ka = kst * 16 + 2 * q;          // k rel. to chunk
        uint2 v;
        v.x = bf16pair(sY[ka * 72 + n],       sY[(ka + 1) * 72 + n]);
        v.y = bf16pair(sY[(ka + 8) * 72 + n], sY[(ka + 9) * 72 + n]);
        *(uint2*)((char*)g_Bp + (size_t)b * B_BYTES + u * 8) = v;
    }
}

// ---------------------------------------------------------------- loader
__device__ __forceinline__ void load_chunk(uint32_t sdst, const float* wp,
                                           const char* bp, const float* sp,
                                           int tid) {
#pragma unroll
    for (int u = 0; u < 8; u++) {
        int idx = tid + u * 128;                      // A: 128 rows x 8 float4
        int r = idx >> 3, sg = idx & 7;
        cp_async16(sdst + (uint32_t)(r * RS + sg * 4) * 4,
                   wp + (size_t)r * N_DIM + sg * 4);
    }
#pragma unroll
    for (int u = 0; u < 2; u++) {                     // B pack: 4KB
        int idx = tid + u * 128;
        cp_async16(sdst + B_OFF + idx * 16, bp + idx * 16);
    }
    if (tid < 8)                                      // sq_k: 128B
        cp_async16(sdst + SQ_OFF * 4 + tid * 16, sp + tid * 4);
}

// ---------------------------------------------------------------- main
__global__ void __launch_bounds__(128, 4)
spec_main(const float* __restrict__ W, const float* __restrict__ Y,
          float* __restrict__ out) {
    extern __shared__ float smem[];
    const uint32_t sb = smem_u32(smem);

    const int tid = threadIdx.x;
    const int w   = tid >> 5;          // warp 0..3: rows [w*32, w*32+32)
    const int lid = tid & 31;
    const int q   = lid & 3;
    const int g   = lid >> 2;
    const int w32 = w * 32;

    const int bx    = blockIdx.x;
    const int mtile = bx & 63;
    const int ks    = bx >> 6;                              // 0..8
    const int m0    = mtile * M_TILE;
    const int c0    = (ks < 4) ? ks * 29 : 116 + (ks - 4) * 28;
    const int nch   = (ks < 4) ? 29 : 28;

    const float* wbase = W + (size_t)m0 * N_DIM + (size_t)c0 * KCHUNK;
    const char*  bbase = (const char*)g_Bp + (size_t)c0 * B_BYTES;

    // row squared-norms for this thread's 4 fragment rows
    const int rbase = m0 + w32 + g;
    float sqi[2][2];
    sqi[0][0] = g_sq[rbase];      sqi[0][1] = g_sq[rbase + 8];
    sqi[1][0] = g_sq[rbase + 16]; sqi[1][1] = g_sq[rbase + 24];

    float acc[2][8][4];
#pragma unroll
    for (int mt = 0; mt < 2; mt++)
#pragma unroll
        for (int nt = 0; nt < 8; nt++)
#pragma unroll
            for (int v = 0; v < 4; v++) acc[mt][nt][v] = 0.0f;
    float scal = 0.0f;

    // prologue: chunk 0 in flight
    load_chunk(sb, wbase, bbase, g_sq + (size_t)c0 * KCHUNK, tid);
    cp_commit();

    for (int j = 0; j < nch; j++) {
        if (j + 1 < nch) {
            load_chunk(sb + ((j + 1) & 1) * STAGE_BYTES,
                       wbase + (size_t)(j + 1) * KCHUNK,
                       bbase + (size_t)(j + 1) * B_BYTES,
                       g_sq + (size_t)(c0 + j + 1) * KCHUNK, tid);
            cp_commit();
            cp_wait1();
        } else {
            cp_wait0();
        }
        __syncthreads();

        const float* As = smem + (j & 1) * STAGE_FLOATS;
        const float* Ss = As + SQ_OFF;
        const char*  Bb = (const char*)smem + (j & 1) * STAGE_BYTES + B_OFF +
                          lid * 8;

#pragma unroll
        for (int kst = 0; kst < 2; kst++) {
            const int k0 = kst * 16 + 2 * q;
            // sq_k pairs for this thread's k slots
            float2 sqa = *(const float2*)(Ss + k0);
            float2 sqb = *(const float2*)(Ss + k0 + 8);

            // A fragments: 4x conflict-free LDS.64 per mt (fp32), cvt to bf16x2
            uint32_t a[2][4];
#pragma unroll
            for (int mt = 0; mt < 2; mt++) {
                const float* ap = As + (w32 + mt * 16 + g) * RS + k0;
                float2 p00 = *(const float2*)ap;             // row g,   k 2q,2q+1
                float2 p01 = *(const float2*)(ap + 8);       // row g,   k +8
                float2 p10 = *(const float2*)(ap + 8 * RS);  // row g+8
                float2 p11 = *(const float2*)(ap + 8 * RS + 8);
                scal += p00.x * (sqi[mt][0] + sqa.x) + p00.y * (sqi[mt][0] + sqa.y)
                      + p01.x * (sqi[mt][0] + sqb.x) + p01.y * (sqi[mt][0] + sqb.y)
                      + p10.x * (sqi[mt][1] + sqa.x) + p10.y * (sqi[mt][1] + sqa.y)
                      + p11.x * (sqi[mt][1] + sqb.x) + p11.y * (sqi[mt][1] + sqb.y);
                a[mt][0] = bf16pair(p00.x, p00.y);
                a[mt][1] = bf16pair(p10.x, p10.y);
                a[mt][2] = bf16pair(p01.x, p01.y);
                a[mt][3] = bf16pair(p11.x, p11.y);
            }
            // B fragments: ONE conflict-free LDS.64 per nt (pre-packed bf16)
#pragma unroll
            for (int nt = 0; nt < 8; nt++) {
                uint2 bb = *(const uint2*)(Bb + kst * 2048 + nt * 256);
                mma_bf16(acc[0][nt], a[0], bb.x, bb.y);
                mma_bf16(acc[1][nt], a[1], bb.x, bb.y);
            }
        }
        __syncthreads();
    }

    // ------------- epilogue: fold U with Y, reduce to scalar ---------------
    float dot = 0.0f;
#pragma unroll
    for (int mt = 0; mt < 2; mt++) {
        const int r0 = m0 + w32 + mt * 16 + g;
#pragma unroll
        for (int nt = 0; nt < 8; nt++) {
            const int cc = nt * 8 + 2 * q;
            float2 y0 = *(const float2*)(Y + (size_t)r0 * KF + cc);
            float2 y1 = *(const float2*)(Y + (size_t)(r0 + 8) * KF + cc);
            dot += acc[mt][nt][0] * y0.x + acc[mt][nt][1] * y0.y +
                   acc[mt][nt][2] * y1.x + acc[mt][nt][3] * y1.y;
        }
    }
    float total = scal - 2.0f * dot;
#pragma unroll
    for (int o = 16; o; o >>= 1)
        total += __shfl_xor_sync(0xffffffffu, total, o);

    if (lid == 0) smem[w] = total;     // stages dead after final chunk barrier
    __syncthreads();
    if (tid == 0) {
        atomicAdd(out, (smem[0] + smem[1] + smem[2] + smem[3]) *
                           (1.0f / (2.0f * (float)N_DIM)));
    }
}

// ---------------------------------------------------------------- launch
extern "C" void kernel_launch(void* const* d_in, const int* in_sizes, int n_in,
                              void* d_out, int out_size) {
    const float* W = (const float*)d_in[0];
    const float* Y = (const float*)d_in[1];
    float* out = (float*)d_out;

    cudaFuncSetAttribute(spec_main, cudaFuncAttributeMaxDynamicSharedMemorySize,
                         SMEM_BYTES);

    spec_prep<<<N_DIM / 32, 256>>>(Y, out);
    spec_main<<<64 * KSPLIT, 128, SMEM_BYTES>>>(W, Y, out);
}